// round 17
// baseline (speedup 1.0000x reference)
#include <cuda_runtime.h>
#include <cuda_fp16.h>
#include <cstdint>

#define M_TOK 12608   // 64*197
#define M_PAD 12672   // 99*128
#define CIN   768
#define CD    256
#define NE    8192
#define NUNIT (99*64) // token tiles * code tiles
#define NUEXP (99*3)  // token tiles * n tiles (768/256)

// ---- device scratch (allocation-free per harness rules) ----
__device__ float g_zf[M_TOK * CD];
__device__ float g_enorm[NE];
__device__ __half g_Ah[(size_t)M_PAD * 512];   // [zh(256) | zm(256)] per token
__device__ __half g_Eh[(size_t)NE * 512];      // [eh(256) | em(256)] per code
__device__ __half g_Wt[(size_t)CIN * 512];     // transposed We splits per n-row
__device__ __half g_Zs[(size_t)M_PAD * 1536];  // input z splits: [zh(768) | zm(768)]
__device__ __half g_Wcs[(size_t)CD * 1536];    // transposed Wc splits per n-row
__device__ unsigned long long g_best[M_TOK];   // packed (sortable-dist << 32) | idx
__device__ int   g_idx[M_TOK];
__device__ float g_lpart[M_TOK / 64];

// ======================= PTX helpers ========================================
__device__ __forceinline__ uint32_t smem_u32(const void* p) {
    uint32_t a;
    asm("{ .reg .u64 t; cvta.to.shared.u64 t, %1; cvt.u32.u64 %0, t; }" : "=r"(a) : "l"(p));
    return a;
}
#define CPASYNC16(dst, src) asm volatile("cp.async.cg.shared.global [%0], [%1], 16;" :: "r"(dst), "l"(src) : "memory")
#define CPCOMMIT() asm volatile("cp.async.commit_group;" ::: "memory")
#define CPWAIT1()  asm volatile("cp.async.wait_group 1;" ::: "memory")
#define CPWAIT0()  asm volatile("cp.async.wait_group 0;" ::: "memory")

__device__ __forceinline__ void ldsm_x4(uint32_t& r0, uint32_t& r1, uint32_t& r2,
                                        uint32_t& r3, uint32_t addr) {
    asm volatile("ldmatrix.sync.aligned.m8n8.x4.shared.b16 {%0,%1,%2,%3}, [%4];"
                 : "=r"(r0), "=r"(r1), "=r"(r2), "=r"(r3) : "r"(addr));
}
__device__ __forceinline__ void mma16816(float* c, const uint32_t* a, const uint32_t* b) {
    asm volatile(
        "mma.sync.aligned.m16n8k16.row.col.f32.f16.f16.f32 "
        "{%0,%1,%2,%3}, {%4,%5,%6,%7}, {%8,%9}, {%0,%1,%2,%3};"
        : "+f"(c[0]), "+f"(c[1]), "+f"(c[2]), "+f"(c[3])
        : "r"(a[0]), "r"(a[1]), "r"(a[2]), "r"(a[3]), "r"(b[0]), "r"(b[1]));
}
// monotone float->uint mapping: min over uint == min over float
__device__ __forceinline__ uint32_t f2sortable(float f) {
    uint32_t u = __float_as_uint(f);
    return u ^ (uint32_t)(((int32_t)u >> 31) | 0x80000000);
}

// ===================== prep E: ||e||^2 + fp16 2-way split ===================
__global__ void k_prepE(const float* __restrict__ E) {
    __shared__ float red[8];
    int row = blockIdx.x, c = threadIdx.x;
    float v = E[(size_t)row * CD + c];
    __half h = __float2half_rn(v);
    float r = v - __half2float(h);
    __half m = __float2half_rn(r);
    size_t b = (size_t)row * 512;
    g_Eh[b + c] = h; g_Eh[b + 256 + c] = m;
    float s = v * v;
#pragma unroll
    for (int off = 16; off > 0; off >>= 1) s += __shfl_down_sync(0xffffffffu, s, off);
    if ((c & 31) == 0) red[c >> 5] = s;
    __syncthreads();
    if (c == 0) {
        float t = 0.f;
#pragma unroll
        for (int w = 0; w < 8; w++) t += red[w];
        g_enorm[row] = t;
    }
}

// ===================== transpose + split We -> g_Wt ========================
__global__ void k_splitWt(const float* __restrict__ We) {
    __shared__ float t[32][33];
    int k0 = blockIdx.x * 32, n0 = blockIdx.y * 32;
    int tx = threadIdx.x, ty = threadIdx.y;  // 32 x 8
#pragma unroll
    for (int r = 0; r < 32; r += 8)
        t[ty + r][tx] = We[(size_t)(k0 + ty + r) * CIN + n0 + tx];
    __syncthreads();
#pragma unroll
    for (int r = 0; r < 32; r += 8) {
        int n = n0 + ty + r, k = k0 + tx;
        float v = t[tx][ty + r];
        __half h = __float2half_rn(v);
        __half m = __float2half_rn(v - __half2float(h));
        g_Wt[(size_t)n * 512 + k] = h;
        g_Wt[(size_t)n * 512 + 256 + k] = m;
    }
}

// ===================== transpose + split Wc -> g_Wcs =======================
__global__ void k_splitWc(const float* __restrict__ Wc) {
    __shared__ float t[32][33];
    int k0 = blockIdx.x * 32, n0 = blockIdx.y * 32;
    int tx = threadIdx.x, ty = threadIdx.y;  // 32 x 8
#pragma unroll
    for (int r = 0; r < 32; r += 8)
        t[ty + r][tx] = Wc[(size_t)(k0 + ty + r) * CD + n0 + tx];
    __syncthreads();
#pragma unroll
    for (int r = 0; r < 32; r += 8) {
        int n = n0 + ty + r, k = k0 + tx;
        float v = t[tx][ty + r];
        __half h = __float2half_rn(v);
        __half m = __float2half_rn(v - __half2float(h));
        g_Wcs[(size_t)n * 1536 + k] = h;
        g_Wcs[(size_t)n * 1536 + 768 + k] = m;
    }
}

// ===================== split input z -> g_Zs  (+ init g_best) ==============
__global__ void k_splitZin(const float* __restrict__ Z) {
    int row = blockIdx.x, c = threadIdx.x;
    if (c == 0 && row < M_TOK) g_best[row] = ~0ull;
    size_t b = (size_t)row * 1536;
#pragma unroll
    for (int j = 0; j < 3; j++) {
        int cc = j * 256 + c;
        float v = (row < M_TOK) ? Z[(size_t)row * CIN + cc] : 0.f;
        __half h = __float2half_rn(v);
        __half m = __float2half_rn(v - __half2float(h));
        g_Zs[b + cc] = h;
        g_Zs[b + 768 + cc] = m;
    }
}

// ===================== HMMA compress: zf = z @ Wc + bc =====================
// grid (2, 99): unit = 128 tok x 128 cols; 256 threads (8 warps, 4m x 2n).
// K = 3 segs x 768 = 36 chunks of 64: A {zh, zm, zh}, B {wh, wh, wm}.
#define CS_STAGE 32768
#define CSA(st) ((st) * CS_STAGE)
#define CSB(st) ((st) * CS_STAGE + 16384)
#define SMEM_CMP 98304

__global__ __launch_bounds__(256, 1) void k_compressH(const float* __restrict__ bias) {
    extern __shared__ char sm[];
    uint32_t sb = smem_u32(sm);
    int tid = threadIdx.x, lane = tid & 31, wid = tid >> 5;
    int wm = wid >> 1, wn = wid & 1;
    int q = lane >> 3, rw = lane & 7;

    uint32_t aRow = (uint32_t)((wm * 32 + ((q & 1) << 3) + rw) * 128);
    uint32_t aKq = (uint32_t)((q >> 1) << 4);
    uint32_t bRow = (uint32_t)((wn * 64 + ((q >> 1) << 3) + rw) * 128);
    uint32_t bKq = (uint32_t)((q & 1) << 4);
    uint32_t swz = (uint32_t)(rw << 4);

    int col0 = blockIdx.x * 128, tok0 = blockIdx.y * 128;

    float acc[2][8][4];
#pragma unroll
    for (int mt = 0; mt < 2; mt++)
#pragma unroll
        for (int nt = 0; nt < 8; nt++)
#pragma unroll
            for (int e = 0; e < 4; e++) acc[mt][nt][e] = 0.f;

    auto load = [&](int c, int st) {
        int seg = c / 12, w = c % 12;
        int aoff = ((seg == 1) ? 768 : 0) + w * 64;  // zh, zm, zh
        int boff = ((seg == 2) ? 768 : 0) + w * 64;  // wh, wh, wm
#pragma unroll
        for (int t = 0; t < 4; t++) {  // A: 128 rows x 128B
            int uu = tid + t * 256;
            int row = uu >> 3, q8 = uu & 7;
            const void* src = &g_Zs[(size_t)(tok0 + row) * 1536 + aoff + q8 * 8];
            int bo = row * 128 + q8 * 16;
            CPASYNC16(sb + CSA(st) + (uint32_t)(bo ^ ((row & 7) << 4)), src);
        }
#pragma unroll
        for (int t = 0; t < 4; t++) {  // B: 128 rows x 128B
            int uu = tid + t * 256;
            int row = uu >> 3, q8 = uu & 7;
            const void* src = &g_Wcs[(size_t)(col0 + row) * 1536 + boff + q8 * 8];
            int bo = row * 128 + q8 * 16;
            CPASYNC16(sb + CSB(st) + (uint32_t)(bo ^ ((row & 7) << 4)), src);
        }
        CPCOMMIT();
    };

    load(0, 0);
    load(1, 1);
    for (int cc = 0; cc < 12; cc++) {
#pragma unroll
        for (int s3 = 0; s3 < 3; s3++) {
            int c = cc * 3 + s3;
            if (c < 35) CPWAIT1(); else CPWAIT0();
            __syncthreads();
            if (c + 2 < 36) load(c + 2, (s3 + 2) % 3);
#pragma unroll
            for (int ks = 0; ks < 4; ks++) {
                uint32_t a[2][4];
#pragma unroll
                for (int mt = 0; mt < 2; mt++)
                    ldsm_x4(a[mt][0], a[mt][1], a[mt][2], a[mt][3],
                            sb + CSA(s3) + aRow + mt * 2048 + (((uint32_t)(ks * 32) + aKq) ^ swz));
                uint32_t b[8][2];
#pragma unroll
                for (int p = 0; p < 4; p++)
                    ldsm_x4(b[2 * p][0], b[2 * p][1], b[2 * p + 1][0], b[2 * p + 1][1],
                            sb + CSB(s3) + bRow + p * 2048 + (((uint32_t)(ks * 32) + bKq) ^ swz));
#pragma unroll
                for (int mt = 0; mt < 2; mt++)
#pragma unroll
                    for (int nt = 0; nt < 8; nt++)
                        mma16816(acc[mt][nt], a[mt], b[nt]);
            }
        }
    }

    // epilogue: zf = acc + bc ; also write fp16 2-way split into g_Ah
#pragma unroll
    for (int nt = 0; nt < 8; nt++) {
        int col = col0 + wn * 64 + nt * 8 + 2 * (lane & 3);
        float b0 = __ldg(&bias[col]), b1 = __ldg(&bias[col + 1]);
#pragma unroll
        for (int mt = 0; mt < 2; mt++) {
#pragma unroll
            for (int key = 0; key < 2; key++) {
                int tok = tok0 + wm * 32 + mt * 16 + key * 8 + (lane >> 2);
                if (tok < M_TOK) {
                    float v0 = acc[mt][nt][key * 2 + 0] + b0;
                    float v1 = acc[mt][nt][key * 2 + 1] + b1;
                    float2 o = {v0, v1};
                    *(float2*)&g_zf[(size_t)tok * CD + col] = o;
                    __half h0 = __float2half_rn(v0), h1 = __float2half_rn(v1);
                    __half m0 = __float2half_rn(v0 - __half2float(h0));
                    __half m1 = __float2half_rn(v1 - __half2float(h1));
                    *(__half2*)&g_Ah[(size_t)tok * 512 + col] = __halves2half2(h0, h1);
                    *(__half2*)&g_Ah[(size_t)tok * 512 + 256 + col] = __halves2half2(m0, m1);
                }
            }
        }
    }
}

// ===================== HMMA distance + fused atomic argmin ==================
// Persistent grid=296 (2 CTAs/SM), 256 threads (8 warps, 4m x 2n).
// Unit = 128 tokens x 128 codes. K = 3 segs x 256 = 12 chunks of 64:
// A {zh,zm,zh}, B {eh,eh,em}. 3-stage ring + cross-unit prefetch.
// Argmin: quad shuffle reduce -> packed atomicMin (no smem reduce, no k_pick).
#define DS_STAGE 32768
#define DSA(st) ((st) * DS_STAGE)
#define DSB(st) ((st) * DS_STAGE + 16384)
#define SMEM_DIST 98304

__device__ __forceinline__ void dist_load(uint32_t sb, int tid,
                                          const __half* Abase, const __half* Bbase,
                                          int c, int st, bool valid) {
    if (valid) {
        int seg = c >> 2, w = c & 3;
        int aoff = ((seg == 1) ? 256 : 0) + w * 64;  // zh, zm, zh
        int boff = ((seg == 2) ? 256 : 0) + w * 64;  // eh, eh, em
#pragma unroll
        for (int t = 0; t < 4; t++) {
            int uu = tid + t * 256;
            int row = uu >> 3, q8 = uu & 7;
            const void* src = Abase + (size_t)row * 512 + aoff + q8 * 8;
            int bo = row * 128 + q8 * 16;
            CPASYNC16(sb + DSA(st) + (uint32_t)(bo ^ ((row & 7) << 4)), src);
        }
#pragma unroll
        for (int t = 0; t < 4; t++) {
            int uu = tid + t * 256;
            int row = uu >> 3, q8 = uu & 7;
            const void* src = Bbase + (size_t)row * 512 + boff + q8 * 8;
            int bo = row * 128 + q8 * 16;
            CPASYNC16(sb + DSB(st) + (uint32_t)(bo ^ ((row & 7) << 4)), src);
        }
    }
    CPCOMMIT();
}

__global__ __launch_bounds__(256, 2) void k_dist() {
    extern __shared__ char sm[];
    uint32_t sb = smem_u32(sm);
    int tid = threadIdx.x, lane = tid & 31, wid = tid >> 5;
    int wm = wid >> 1, wn = wid & 1;
    int q = lane >> 3, rw = lane & 7;

    uint32_t aRow = (uint32_t)((wm * 32 + ((q & 1) << 3) + rw) * 128);
    uint32_t aKq = (uint32_t)((q >> 1) << 4);
    uint32_t bRow = (uint32_t)((wn * 64 + ((q >> 1) << 3) + rw) * 128);
    uint32_t bKq = (uint32_t)((q & 1) << 4);
    uint32_t swz = (uint32_t)(rw << 4);

    int u = blockIdx.x;
    const __half* Ab = &g_Ah[(size_t)(u >> 6) * 128 * 512];
    const __half* Bb = &g_Eh[(size_t)(u & 63) * 128 * 512];
    dist_load(sb, tid, Ab, Bb, 0, 0, u < NUNIT);
    dist_load(sb, tid, Ab, Bb, 1, 1, u < NUNIT);

    for (; u < NUNIT; u += gridDim.x) {
        int tt = u >> 6, ct = u & 63;
        int tok0 = tt * 128, c0 = ct * 128;
        int un = u + gridDim.x;
        const __half* Abn = &g_Ah[(size_t)(un >> 6) * 128 * 512];
        const __half* Bbn = &g_Eh[(size_t)(un & 63) * 128 * 512];

        float acc[2][8][4];
#pragma unroll
        for (int mt = 0; mt < 2; mt++)
#pragma unroll
            for (int nt = 0; nt < 8; nt++)
#pragma unroll
                for (int e = 0; e < 4; e++) acc[mt][nt][e] = 0.f;

        for (int cc = 0; cc < 4; cc++) {
#pragma unroll
            for (int s3 = 0; s3 < 3; s3++) {
                int c = cc * 3 + s3;
                CPWAIT1();
                __syncthreads();
                if (c < 10) dist_load(sb, tid, Ab, Bb, c + 2, (s3 + 2) % 3, true);
                else        dist_load(sb, tid, Abn, Bbn, c - 10, (s3 + 2) % 3, un < NUNIT);
#pragma unroll
                for (int ks = 0; ks < 4; ks++) {
                    uint32_t a[2][4];
#pragma unroll
                    for (int mt = 0; mt < 2; mt++)
                        ldsm_x4(a[mt][0], a[mt][1], a[mt][2], a[mt][3],
                                sb + DSA(s3) + aRow + mt * 2048 + (((uint32_t)(ks * 32) + aKq) ^ swz));
                    uint32_t b[8][2];
#pragma unroll
                    for (int p = 0; p < 4; p++)
                        ldsm_x4(b[2 * p][0], b[2 * p][1], b[2 * p + 1][0], b[2 * p + 1][1],
                                sb + DSB(s3) + bRow + p * 2048 + (((uint32_t)(ks * 32) + bKq) ^ swz));
#pragma unroll
                    for (int mt = 0; mt < 2; mt++)
#pragma unroll
                        for (int nt = 0; nt < 8; nt++)
                            mma16816(acc[mt][nt], a[mt], b[nt]);
                }
            }
        }

        // epilogue: d = ||e||^2 - 2 z.e ; strict < keeps lowest index
        float bestv[2][2]; int besti[2][2];
#pragma unroll
        for (int mt = 0; mt < 2; mt++)
#pragma unroll
            for (int key = 0; key < 2; key++) { bestv[mt][key] = 3.4e38f; besti[mt][key] = 0; }
#pragma unroll
        for (int nt = 0; nt < 8; nt++) {
            int colb = c0 + wn * 64 + nt * 8 + 2 * (lane & 3);
            float en0 = __ldg(&g_enorm[colb]);
            float en1 = __ldg(&g_enorm[colb + 1]);
#pragma unroll
            for (int mt = 0; mt < 2; mt++) {
#pragma unroll
                for (int key = 0; key < 2; key++) {
                    float d0 = en0 - 2.0f * acc[mt][nt][key * 2 + 0];
                    if (d0 < bestv[mt][key]) { bestv[mt][key] = d0; besti[mt][key] = colb; }
                    float d1 = en1 - 2.0f * acc[mt][nt][key * 2 + 1];
                    if (d1 < bestv[mt][key]) { bestv[mt][key] = d1; besti[mt][key] = colb + 1; }
                }
            }
        }
#pragma unroll
        for (int mt = 0; mt < 2; mt++)
#pragma unroll
            for (int key = 0; key < 2; key++) {
                float v = bestv[mt][key]; int bi = besti[mt][key];
#pragma unroll
                for (int off = 1; off <= 2; off <<= 1) {
                    float ov = __shfl_xor_sync(0xffffffffu, v, off);
                    int   oi = __shfl_xor_sync(0xffffffffu, bi, off);
                    if (ov < v || (ov == v && oi < bi)) { v = ov; bi = oi; }
                }
                if ((lane & 3) == 0) {
                    int tok = tok0 + wm * 32 + mt * 16 + key * 8 + (lane >> 2);
                    if (tok < M_TOK) {
                        unsigned long long pk =
                            ((unsigned long long)f2sortable(v) << 32) | (uint32_t)bi;
                        atomicMin(&g_best[tok], pk);
                    }
                }
            }
        Ab = Abn; Bb = Bbn;
    }
}

// ===================== unpack argmin index ==================================
__global__ void k_pick() {
    int m = blockIdx.x * blockDim.x + threadIdx.x;
    if (m < M_TOK) g_idx[m] = (int)(g_best[m] & 0xFFFFFFFFu);
}

// ===================== HMMA expand: out = emb[idx] @ We + be ================
#define ES_STAGE 49152
#define ESA(st) ((st) * ES_STAGE)
#define ESB(st) ((st) * ES_STAGE + 16384)
#define EX_IDX 147456
#define SMEM_EXP 147968

__global__ __launch_bounds__(512, 1) void k_expand(const float* __restrict__ bias,
                                                   float* __restrict__ out) {
    extern __shared__ char sm[];
    uint32_t sb = smem_u32(sm);
    int* idxS = (int*)(sm + EX_IDX);
    int tid = threadIdx.x, lane = tid & 31, wid = tid >> 5;
    int wm = wid >> 2, wn = wid & 3;
    int q = lane >> 3, rw = lane & 7;

    uint32_t aRow = (uint32_t)((wm * 32 + ((q & 1) << 3) + rw) * 128);
    uint32_t aKq = (uint32_t)((q >> 1) << 4);
    uint32_t bRow = (uint32_t)((wn * 64 + ((q >> 1) << 3) + rw) * 128);
    uint32_t bKq = (uint32_t)((q & 1) << 4);
    uint32_t swz = (uint32_t)(rw << 4);

    int u = blockIdx.x;
    int tt = u / 3, n3 = u - tt * 3;
    int tok0 = tt * 128, ncol0 = n3 * 256;

    if (tid < 128) {
        int tok = tok0 + tid;
        idxS[tid] = (tok < M_TOK) ? g_idx[tok] : 0;
    }
    __syncthreads();

    const __half* Bbase = &g_Wt[(size_t)ncol0 * 512];

    float acc[2][8][4];
#pragma unroll
    for (int mt = 0; mt < 2; mt++)
#pragma unroll
        for (int nt = 0; nt < 8; nt++)
#pragma unroll
            for (int e = 0; e < 4; e++) acc[mt][nt][e] = 0.f;

    auto load = [&](int c, int st) {
        int seg = c >> 2, w = c & 3;
        int aoff = ((seg == 1) ? 256 : 0) + w * 64;  // eh, em, eh
        int boff = ((seg == 2) ? 256 : 0) + w * 64;  // wh, wh, wm
#pragma unroll
        for (int t = 0; t < 2; t++) {
            int uu = tid + t * 512;
            int row = uu >> 3, q8 = uu & 7;
            const void* src = &g_Eh[(size_t)idxS[row] * 512 + aoff + q8 * 8];
            int bo = row * 128 + q8 * 16;
            CPASYNC16(sb + ESA(st) + (uint32_t)(bo ^ ((row & 7) << 4)), src);
        }
#pragma unroll
        for (int t = 0; t < 4; t++) {
            int uu = tid + t * 512;
            int row = uu >> 3, q8 = uu & 7;
            const void* src = Bbase + (size_t)row * 512 + boff + q8 * 8;
            int bo = row * 128 + q8 * 16;
            CPASYNC16(sb + ESB(st) + (uint32_t)(bo ^ ((row & 7) << 4)), src);
        }
        CPCOMMIT();
    };

    load(0, 0);
    load(1, 1);
    for (int cc = 0; cc < 4; cc++) {
#pragma unroll
        for (int s3 = 0; s3 < 3; s3++) {
            int c = cc * 3 + s3;
            if (c < 11) CPWAIT1(); else CPWAIT0();
            __syncthreads();
            if (c + 2 < 12) load(c + 2, (s3 + 2) % 3);
#pragma unroll
            for (int ks = 0; ks < 4; ks++) {
                uint32_t a[2][4];
#pragma unroll
                for (int mt = 0; mt < 2; mt++)
                    ldsm_x4(a[mt][0], a[mt][1], a[mt][2], a[mt][3],
                            sb + ESA(s3) + aRow + mt * 2048 + (((uint32_t)(ks * 32) + aKq) ^ swz));
                uint32_t b[8][2];
#pragma unroll
                for (int p = 0; p < 4; p++)
                    ldsm_x4(b[2 * p][0], b[2 * p][1], b[2 * p + 1][0], b[2 * p + 1][1],
                            sb + ESB(s3) + bRow + p * 2048 + (((uint32_t)(ks * 32) + bKq) ^ swz));
#pragma unroll
                for (int mt = 0; mt < 2; mt++)
#pragma unroll
                    for (int nt = 0; nt < 8; nt++)
                        mma16816(acc[mt][nt], a[mt], b[nt]);
            }
        }
    }

#pragma unroll
    for (int nt = 0; nt < 8; nt++) {
        int col = ncol0 + wn * 64 + nt * 8 + 2 * (lane & 3);
        float b0 = __ldg(&bias[col]), b1 = __ldg(&bias[col + 1]);
#pragma unroll
        for (int mt = 0; mt < 2; mt++) {
#pragma unroll
            for (int key = 0; key < 2; key++) {
                int tok = tok0 + wm * 32 + mt * 16 + key * 8 + (lane >> 2);
                if (tok < M_TOK) {
                    float2 o = {acc[mt][nt][key * 2 + 0] + b0, acc[mt][nt][key * 2 + 1] + b1};
                    *(float2*)&out[(size_t)tok * CIN + col] = o;
                }
            }
        }
    }
}

// ===================== loss partials =====================
__global__ void k_loss(const float* __restrict__ E) {
    __shared__ int idxS[64];
    __shared__ float red[256];
    int row0 = blockIdx.x * 64;
    if (threadIdx.x < 64) idxS[threadIdx.x] = g_idx[row0 + threadIdx.x];
    __syncthreads();
    float s = 0.f;
    for (int idx = threadIdx.x; idx < 64 * CD; idx += 256) {
        int r = idx >> 8, k = idx & 255;
        float d = E[(size_t)idxS[r] * CD + k] - g_zf[(size_t)(row0 + r) * CD + k];
        s += d * d;
    }
    red[threadIdx.x] = s;
    __syncthreads();
    for (int off = 128; off > 0; off >>= 1) {
        if (threadIdx.x < off) red[threadIdx.x] += red[threadIdx.x + off];
        __syncthreads();
    }
    if (threadIdx.x == 0) g_lpart[blockIdx.x] = red[0];
}

__global__ void k_final(float* out_loss) {
    __shared__ float red[256];
    float s = (threadIdx.x < M_TOK / 64) ? g_lpart[threadIdx.x] : 0.f;
    red[threadIdx.x] = s;
    __syncthreads();
    for (int off = 128; off > 0; off >>= 1) {
        if (threadIdx.x < off) red[threadIdx.x] += red[threadIdx.x + off];
        __syncthreads();
    }
    if (threadIdx.x == 0) out_loss[0] = 3.0f * red[0] / (float)((size_t)M_TOK * CD);
}

extern "C" void kernel_launch(void* const* d_in, const int* in_sizes, int n_in,
                              void* d_out, int out_size) {
    const float* z   = (const float*)d_in[0];
    const float* emb = (const float*)d_in[1];
    const float* Wc  = (const float*)d_in[2];
    const float* bc  = (const float*)d_in[3];
    const float* We  = (const float*)d_in[4];
    const float* be  = (const float*)d_in[5];
    float* out = (float*)d_out;

    cudaFuncSetAttribute(k_compressH, cudaFuncAttributeMaxDynamicSharedMemorySize, SMEM_CMP);
    cudaFuncSetAttribute(k_dist, cudaFuncAttributeMaxDynamicSharedMemorySize, SMEM_DIST);
    cudaFuncSetAttribute(k_expand, cudaFuncAttributeMaxDynamicSharedMemorySize, SMEM_EXP);

    k_prepE<<<NE, 256>>>(emb);
    k_splitWt<<<dim3(8, 24), dim3(32, 8)>>>(We);
    k_splitWc<<<dim3(24, 8), dim3(32, 8)>>>(Wc);
    k_splitZin<<<M_PAD, 256>>>(z);
    k_compressH<<<dim3(2, M_PAD / 128), 256, SMEM_CMP>>>(bc);
    k_dist<<<296, 256, SMEM_DIST>>>();
    k_pick<<<(M_TOK + 255) / 256, 256>>>();
    k_expand<<<NUEXP, 512, SMEM_EXP>>>(be, out);
    k_loss<<<M_TOK / 64, 256>>>(emb);
    if (out_size > M_TOK * CIN) k_final<<<1, 256>>>(out + (size_t)M_TOK * CIN);
}